// round 1
// baseline (speedup 1.0000x reference)
#include <cuda_runtime.h>
#include <cstdint>

#define CCH 32
#define HH 224
#define WW 224
#define BB 16
#define KELEMS (CCH*9)   // 288 weight elems per out channel

// Binarized conv1 weights, layout [ci][k][co], values {-1,0,+1} as float
__device__ float g_w1[CCH*9*CCH];
// Binarized conv2 weights packed int8x4 over ci groups: [cig][k][co]
__device__ int   g_w2[(CCH/4)*9*CCH];
// LUT params
__device__ float g_lut1_t0[CCH], g_lut1_d[CCH];
__device__ int   g_lut2_t0[CCH], g_lut2_d[CCH];
// Intermediate levels, 4 channels packed per uint32: [n][cig][h][w]
__device__ unsigned int g_mid[(size_t)BB*(CCH/4)*HH*WW];

__device__ __forceinline__ float sgnf(float v) {
    return (v > 0.f) ? 1.f : ((v < 0.f) ? -1.f : 0.f);
}

// ---------------------------------------------------------------------------
// Setup: binarize weights (sign(w - mean_c)) and fold BN into integer LUTs
// ---------------------------------------------------------------------------
__global__ void setup_kernel(const float* __restrict__ conv1_w,
                             const float* __restrict__ conv2_w,
                             const float* __restrict__ bn1_w, const float* __restrict__ bn1_b,
                             const float* __restrict__ bn1_m, const float* __restrict__ bn1_v,
                             const float* __restrict__ bn2_w, const float* __restrict__ bn2_b,
                             const float* __restrict__ bn2_m, const float* __restrict__ bn2_v,
                             const float* __restrict__ a1p, const float* __restrict__ a2p,
                             const float* __restrict__ nsp) {
    __shared__ float red[KELEMS];
    __shared__ float mean1s, mean2s;
    __shared__ int   ssm[KELEMS];
    int co = blockIdx.x;
    int t  = threadIdx.x;           // 288 threads

    float v1 = conv1_w[co*KELEMS + t];
    float v2 = conv2_w[co*KELEMS + t];

    // mean of conv1_w[co]
    red[t] = v1; __syncthreads();
    if (t < 32) red[t] += red[t + 256];
    __syncthreads();
    for (int s = 128; s > 0; s >>= 1) { if (t < s) red[t] += red[t + s]; __syncthreads(); }
    if (t == 0) mean1s = red[0] * (1.f / 288.f);
    __syncthreads();
    float m1 = mean1s;
    __syncthreads();

    // mean of conv2_w[co]
    red[t] = v2; __syncthreads();
    if (t < 32) red[t] += red[t + 256];
    __syncthreads();
    for (int s = 128; s > 0; s >>= 1) { if (t < s) red[t] += red[t + s]; __syncthreads(); }
    if (t == 0) mean2s = red[0] * (1.f / 288.f);
    __syncthreads();
    float m2 = mean2s;

    int ci = t / 9, k = t % 9;
    g_w1[(ci*9 + k)*CCH + co] = sgnf(v1 - m1);

    float s2f = v2 - m2;
    ssm[t] = (s2f > 0.f) ? 1 : ((s2f < 0.f) ? -1 : 0);
    __syncthreads();
    if (t < (CCH/4)*9) {
        int cig = t / 9, kk = t % 9;
        int pk = 0;
        #pragma unroll
        for (int b = 0; b < 4; b++) {
            int s = ssm[(cig*4 + b)*9 + kk];
            pk |= (s & 0xFF) << (8*b);
        }
        g_w2[(cig*9 + kk)*CCH + co] = pk;
    }

    if (t == 0) {
        float a1 = *a1p, a2 = *a2p, ns = *nsp;
        {
            float std = sqrtf(bn1_v[co] + 1e-5f);
            float w = bn1_w[co] / std;
            float b = bn1_b[co] - w * bn1_m[co];
            float den = a1 * w;
            float t0 = rintf((0.5f * a2 - b) / den);
            float t1 = rintf((1.5f * a2 - b) / den);
            g_lut1_t0[co] = t0;
            g_lut1_d[co]  = t1 - t0;
        }
        {
            float std = sqrtf(bn2_v[co] + 1e-5f);
            float w = bn2_w[co] / std;
            float b = bn2_b[co] - w * bn2_m[co];
            float den = a2 * w;
            float t0 = rintf((0.5f * ns - b) / den);
            float t1 = rintf((1.5f * ns - b) / den);
            g_lut2_t0[co] = (int)t0;
            g_lut2_d[co]  = (int)(t1 - t0);
        }
    }
}

// ---------------------------------------------------------------------------
// Conv1 (fp32, weights ±1) fused with LUT1 -> packed int8 levels
// Block: 16x16 output tile, all 32 out channels. 256 threads:
//   cog = tid>>6 owns 8 out channels, p0 = tid&63 owns 4 pixels.
// ---------------------------------------------------------------------------
__device__ __forceinline__ float load_x(const float* __restrict__ xn, int ci,
                                        int idx, int h0, int w0) {
    int ph = idx / 18, pw = idx % 18;
    int gh = h0 - 1 + ph, gw = w0 - 1 + pw;
    if (gh < 0 || gh >= HH || gw < 0 || gw >= WW) return 0.f;
    return xn[(size_t)ci*HH*WW + gh*WW + gw];
}

__global__ void __launch_bounds__(256, 2)
conv1_kernel(const float* __restrict__ x) {
    __shared__ float ws[CCH*9*CCH];        // 36864 B
    __shared__ float patch[2][18*18];

    int n  = blockIdx.z;
    int h0 = blockIdx.y * 16, w0 = blockIdx.x * 16;
    int tid = threadIdx.x;

    for (int i = tid; i < CCH*9*CCH; i += 256) ws[i] = g_w1[i];

    int cog = tid >> 6;      // 0..3 -> co in [cog*8, cog*8+8)
    int p0  = tid & 63;

    float acc[4][8];
    #pragma unroll
    for (int p = 0; p < 4; p++)
        #pragma unroll
        for (int j = 0; j < 8; j++) acc[p][j] = 0.f;

    const float* xn = x + (size_t)n*CCH*HH*WW;

    float r0 = load_x(xn, 0, tid, h0, w0);
    float r1 = (tid + 256 < 324) ? load_x(xn, 0, tid + 256, h0, w0) : 0.f;

    for (int ci = 0; ci < CCH; ci++) {
        int buf = ci & 1;
        patch[buf][tid] = r0;
        if (tid + 256 < 324) patch[buf][tid + 256] = r1;
        __syncthreads();
        if (ci + 1 < CCH) {
            r0 = load_x(xn, ci + 1, tid, h0, w0);
            r1 = (tid + 256 < 324) ? load_x(xn, ci + 1, tid + 256, h0, w0) : 0.f;
        }
        const float* wp = &ws[ci*9*CCH + cog*8];
        #pragma unroll
        for (int k = 0; k < 9; k++) {
            int kh = k / 3, kw = k % 3;
            float4 wa = *(const float4*)(wp + k*CCH);
            float4 wb = *(const float4*)(wp + k*CCH + 4);
            #pragma unroll
            for (int p = 0; p < 4; p++) {
                int pix = p0 + 64*p;
                int hh = pix >> 4, wc = pix & 15;
                float xv = patch[buf][(hh + kh)*18 + wc + kw];
                acc[p][0] = fmaf(xv, wa.x, acc[p][0]);
                acc[p][1] = fmaf(xv, wa.y, acc[p][1]);
                acc[p][2] = fmaf(xv, wa.z, acc[p][2]);
                acc[p][3] = fmaf(xv, wa.w, acc[p][3]);
                acc[p][4] = fmaf(xv, wb.x, acc[p][4]);
                acc[p][5] = fmaf(xv, wb.y, acc[p][5]);
                acc[p][6] = fmaf(xv, wb.z, acc[p][6]);
                acc[p][7] = fmaf(xv, wb.w, acc[p][7]);
            }
        }
        __syncthreads();
    }

    // LUT1 + pack
    float T0[8], D[8];
    #pragma unroll
    for (int j = 0; j < 8; j++) {
        T0[j] = g_lut1_t0[cog*8 + j];
        D[j]  = g_lut1_d[cog*8 + j];
    }
    #pragma unroll
    for (int p = 0; p < 4; p++) {
        int pix = p0 + 64*p;
        int hh = pix >> 4, wc = pix & 15;
        int gh = h0 + hh, gw = w0 + wc;
        unsigned word0 = 0, word1 = 0;
        #pragma unroll
        for (int j = 0; j < 8; j++) {
            float a = acc[p][j];
            int lvl = 0;
            #pragma unroll
            for (int jj = 0; jj < 7; jj++) {
                float th = T0[j] + (float)jj * D[j];
                lvl += (jj & 1) ? (a >= th) : (a > th);
            }
            if (j < 4) word0 |= (unsigned)lvl << (8*j);
            else       word1 |= (unsigned)lvl << (8*(j-4));
        }
        size_t base = (((size_t)n*(CCH/4) + cog*2)*HH + gh)*WW + gw;
        g_mid[base]           = word0;
        g_mid[base + (size_t)HH*WW] = word1;
    }
}

// ---------------------------------------------------------------------------
// Conv2 (exact int8 via dp4a, weights ±1) fused with LUT2 -> fp32 output
// ---------------------------------------------------------------------------
__device__ __forceinline__ unsigned load_mid(const unsigned* __restrict__ mn, int cig,
                                             int idx, int h0, int w0) {
    int ph = idx / 18, pw = idx % 18;
    int gh = h0 - 1 + ph, gw = w0 - 1 + pw;
    if (gh < 0 || gh >= HH || gw < 0 || gw >= WW) return 0u;
    return mn[(size_t)cig*HH*WW + gh*WW + gw];
}

__global__ void __launch_bounds__(256, 2)
conv2_kernel(float* __restrict__ out) {
    __shared__ int ws2[(CCH/4)*9*CCH];     // 9216 B
    __shared__ unsigned patch[2][18*18];

    int n  = blockIdx.z;
    int h0 = blockIdx.y * 16, w0 = blockIdx.x * 16;
    int tid = threadIdx.x;

    for (int i = tid; i < (CCH/4)*9*CCH; i += 256) ws2[i] = g_w2[i];

    int cog = tid >> 6;
    int p0  = tid & 63;

    int acc[4][8];
    #pragma unroll
    for (int p = 0; p < 4; p++)
        #pragma unroll
        for (int j = 0; j < 8; j++) acc[p][j] = 0;

    const unsigned* mn = g_mid + (size_t)n*(CCH/4)*HH*WW;

    unsigned r0 = load_mid(mn, 0, tid, h0, w0);
    unsigned r1 = (tid + 256 < 324) ? load_mid(mn, 0, tid + 256, h0, w0) : 0u;

    for (int cig = 0; cig < CCH/4; cig++) {
        int buf = cig & 1;
        patch[buf][tid] = r0;
        if (tid + 256 < 324) patch[buf][tid + 256] = r1;
        __syncthreads();
        if (cig + 1 < CCH/4) {
            r0 = load_mid(mn, cig + 1, tid, h0, w0);
            r1 = (tid + 256 < 324) ? load_mid(mn, cig + 1, tid + 256, h0, w0) : 0u;
        }
        const int* wp = &ws2[cig*9*CCH + cog*8];
        #pragma unroll
        for (int k = 0; k < 9; k++) {
            int kh = k / 3, kw = k % 3;
            int4 wa = *(const int4*)(wp + k*CCH);
            int4 wb = *(const int4*)(wp + k*CCH + 4);
            #pragma unroll
            for (int p = 0; p < 4; p++) {
                int pix = p0 + 64*p;
                int hh = pix >> 4, wc = pix & 15;
                int xv = (int)patch[buf][(hh + kh)*18 + wc + kw];
                acc[p][0] = __dp4a(xv, wa.x, acc[p][0]);
                acc[p][1] = __dp4a(xv, wa.y, acc[p][1]);
                acc[p][2] = __dp4a(xv, wa.z, acc[p][2]);
                acc[p][3] = __dp4a(xv, wa.w, acc[p][3]);
                acc[p][4] = __dp4a(xv, wb.x, acc[p][4]);
                acc[p][5] = __dp4a(xv, wb.y, acc[p][5]);
                acc[p][6] = __dp4a(xv, wb.z, acc[p][6]);
                acc[p][7] = __dp4a(xv, wb.w, acc[p][7]);
            }
        }
        __syncthreads();
    }

    int IT0[8], ID[8];
    #pragma unroll
    for (int j = 0; j < 8; j++) {
        IT0[j] = g_lut2_t0[cog*8 + j];
        ID[j]  = g_lut2_d[cog*8 + j];
    }
    #pragma unroll
    for (int p = 0; p < 4; p++) {
        int pix = p0 + 64*p;
        int hh = pix >> 4, wc = pix & 15;
        int gh = h0 + hh, gw = w0 + wc;
        #pragma unroll
        for (int j = 0; j < 8; j++) {
            int s = acc[p][j];
            int lvl = 0;
            #pragma unroll
            for (int jj = 0; jj < 7; jj++) {
                int th = IT0[j] + jj * ID[j];
                lvl += (jj & 1) ? (s >= th) : (s > th);
            }
            int co = cog*8 + j;
            out[(((size_t)n*CCH + co)*HH + gh)*WW + gw] = (float)lvl;
        }
    }
}

// ---------------------------------------------------------------------------
extern "C" void kernel_launch(void* const* d_in, const int* in_sizes, int n_in,
                              void* d_out, int out_size) {
    const float* x       = (const float*)d_in[0];
    const float* conv1_w = (const float*)d_in[1];
    const float* conv2_w = (const float*)d_in[2];
    const float* bn1_w   = (const float*)d_in[3];
    const float* bn1_b   = (const float*)d_in[4];
    const float* bn1_m   = (const float*)d_in[5];
    const float* bn1_v   = (const float*)d_in[6];
    const float* bn2_w   = (const float*)d_in[7];
    const float* bn2_b   = (const float*)d_in[8];
    const float* bn2_m   = (const float*)d_in[9];
    const float* bn2_v   = (const float*)d_in[10];
    const float* a1      = (const float*)d_in[11];
    const float* a2      = (const float*)d_in[12];
    const float* ns      = (const float*)d_in[13];

    setup_kernel<<<CCH, KELEMS>>>(conv1_w, conv2_w,
                                  bn1_w, bn1_b, bn1_m, bn1_v,
                                  bn2_w, bn2_b, bn2_m, bn2_v,
                                  a1, a2, ns);

    dim3 grid(WW/16, HH/16, BB);
    conv1_kernel<<<grid, 256>>>(x);
    conv2_kernel<<<grid, 256>>>((float*)d_out);
}

// round 3
// speedup vs baseline: 1.0003x; 1.0003x over previous
#include <cuda_runtime.h>
#include <cstdint>

#define CCH 32
#define HH 224
#define WW 224
#define BB 16
#define KELEMS (CCH*9)   // 288 weight elems per out channel

// Binarized conv1 weights, layout [ci][k][co], values {-1,0,+1} as float
__device__ float g_w1[CCH*9*CCH];
// Binarized conv2 weights packed int8x4 over ci groups: [cig][k][co]
__device__ int   g_w2[(CCH/4)*9*CCH];
// LUT params
__device__ float g_lut1_t0[CCH], g_lut1_d[CCH];
__device__ int   g_lut2_t0[CCH], g_lut2_d[CCH];
// Intermediate levels, 4 channels packed per uint32: [n][cig][h][w]
__device__ unsigned int g_mid[(size_t)BB*(CCH/4)*HH*WW];

__device__ __forceinline__ float sgnf(float v) {
    return (v > 0.f) ? 1.f : ((v < 0.f) ? -1.f : 0.f);
}

// packed f32x2 helpers (Blackwell)
__device__ __forceinline__ unsigned long long pk2(float lo, float hi) {
    unsigned long long r;
    asm("mov.b64 %0, {%1, %2};" : "=l"(r) : "f"(lo), "f"(hi));
    return r;
}
__device__ __forceinline__ void upk2(unsigned long long v, float& lo, float& hi) {
    asm("mov.b64 {%0, %1}, %2;" : "=f"(lo), "=f"(hi) : "l"(v));
}
#define FMA2(d, a, b) asm("fma.rn.f32x2 %0, %1, %2, %0;" : "+l"(d) : "l"(a), "l"(b))

// ---------------------------------------------------------------------------
// Setup: binarize weights (sign(w - mean_c)) and fold BN into integer LUTs
// ---------------------------------------------------------------------------
__global__ void setup_kernel(const float* __restrict__ conv1_w,
                             const float* __restrict__ conv2_w,
                             const float* __restrict__ bn1_w, const float* __restrict__ bn1_b,
                             const float* __restrict__ bn1_m, const float* __restrict__ bn1_v,
                             const float* __restrict__ bn2_w, const float* __restrict__ bn2_b,
                             const float* __restrict__ bn2_m, const float* __restrict__ bn2_v,
                             const float* __restrict__ a1p, const float* __restrict__ a2p,
                             const float* __restrict__ nsp) {
    __shared__ float red[KELEMS];
    __shared__ float mean1s, mean2s;
    __shared__ int   ssm[KELEMS];
    int co = blockIdx.x;
    int t  = threadIdx.x;           // 288 threads

    float v1 = conv1_w[co*KELEMS + t];
    float v2 = conv2_w[co*KELEMS + t];

    // mean of conv1_w[co]
    red[t] = v1; __syncthreads();
    if (t < 32) red[t] += red[t + 256];
    __syncthreads();
    for (int s = 128; s > 0; s >>= 1) { if (t < s) red[t] += red[t + s]; __syncthreads(); }
    if (t == 0) mean1s = red[0] * (1.f / 288.f);
    __syncthreads();
    float m1 = mean1s;
    __syncthreads();

    // mean of conv2_w[co]
    red[t] = v2; __syncthreads();
    if (t < 32) red[t] += red[t + 256];
    __syncthreads();
    for (int s = 128; s > 0; s >>= 1) { if (t < s) red[t] += red[t + s]; __syncthreads(); }
    if (t == 0) mean2s = red[0] * (1.f / 288.f);
    __syncthreads();
    float m2 = mean2s;

    int ci = t / 9, k = t % 9;
    g_w1[(ci*9 + k)*CCH + co] = sgnf(v1 - m1);

    float s2f = v2 - m2;
    ssm[t] = (s2f > 0.f) ? 1 : ((s2f < 0.f) ? -1 : 0);
    __syncthreads();
    if (t < (CCH/4)*9) {
        int cig = t / 9, kk = t % 9;
        int pk = 0;
        #pragma unroll
        for (int b = 0; b < 4; b++) {
            int s = ssm[(cig*4 + b)*9 + kk];
            pk |= (s & 0xFF) << (8*b);
        }
        g_w2[(cig*9 + kk)*CCH + co] = pk;
    }

    if (t == 0) {
        float a1 = *a1p, a2 = *a2p, ns = *nsp;
        {
            float std = sqrtf(bn1_v[co] + 1e-5f);
            float w = bn1_w[co] / std;
            float b = bn1_b[co] - w * bn1_m[co];
            float den = a1 * w;
            float t0 = rintf((0.5f * a2 - b) / den);
            float t1 = rintf((1.5f * a2 - b) / den);
            g_lut1_t0[co] = t0;
            g_lut1_d[co]  = t1 - t0;
        }
        {
            float std = sqrtf(bn2_v[co] + 1e-5f);
            float w = bn2_w[co] / std;
            float b = bn2_b[co] - w * bn2_m[co];
            float den = a2 * w;
            float t0 = rintf((0.5f * ns - b) / den);
            float t1 = rintf((1.5f * ns - b) / den);
            g_lut2_t0[co] = (int)t0;
            g_lut2_d[co]  = (int)(t1 - t0);
        }
    }
}

// ---------------------------------------------------------------------------
// Conv1 (fp32, weights ±1) via packed fma.rn.f32x2, fused LUT1 -> packed levels
// Block: 16x16 output tile, all 32 out channels. 256 threads:
//   cog = tid>>6 owns 8 out channels, p0 = tid&63 owns 2 pixel-PAIRS (4 pixels).
// ---------------------------------------------------------------------------
__device__ __forceinline__ float load_x(const float* __restrict__ xn, int ci,
                                        int idx, int h0, int w0) {
    int ph = idx / 18, pw = idx % 18;
    int gh = h0 - 1 + ph, gw = w0 - 1 + pw;
    if (gh < 0 || gh >= HH || gw < 0 || gw >= WW) return 0.f;
    return xn[(size_t)ci*HH*WW + gh*WW + gw];
}

__global__ void __launch_bounds__(256, 2)
conv1_kernel(const float* __restrict__ x) {
    __shared__ float ws[CCH*9*CCH];                    // 36864 B
    __shared__ __align__(16) float patch[2][18*18];

    int n  = blockIdx.z;
    int h0 = blockIdx.y * 16, w0 = blockIdx.x * 16;
    int tid = threadIdx.x;

    for (int i = tid; i < CCH*9*CCH; i += 256) ws[i] = g_w1[i];

    int cog = tid >> 6;      // 0..3 -> co in [cog*8, cog*8+8)
    int p0  = tid & 63;
    int hh0 = p0 >> 3;       // row 0..7 (pair p adds +8)
    int wpx = p0 & 7;        // pair column: pixels 2*wpx, 2*wpx+1

    unsigned long long acc[2][8];
    #pragma unroll
    for (int p = 0; p < 2; p++)
        #pragma unroll
        for (int j = 0; j < 8; j++) acc[p][j] = 0ull;

    const float* xn = x + (size_t)n*CCH*HH*WW;

    float r0 = load_x(xn, 0, tid, h0, w0);
    float r1 = (tid + 256 < 324) ? load_x(xn, 0, tid + 256, h0, w0) : 0.f;

    for (int ci = 0; ci < CCH; ci++) {
        int buf = ci & 1;
        patch[buf][tid] = r0;
        if (tid + 256 < 324) patch[buf][tid + 256] = r1;
        __syncthreads();
        if (ci + 1 < CCH) {
            r0 = load_x(xn, ci + 1, tid, h0, w0);
            r1 = (tid + 256 < 324) ? load_x(xn, ci + 1, tid + 256, h0, w0) : 0.f;
        }
        const float* wbase = &ws[ci*9*CCH + cog*8];
        #pragma unroll
        for (int kh = 0; kh < 3; kh++) {
            // gather packed pixel pairs for the 3 kw shifts, both pair-rows
            unsigned long long xv[2][3];
            #pragma unroll
            for (int p = 0; p < 2; p++) {
                int hh = hh0 + 8*p;
                const float* pr = &patch[buf][(hh + kh)*18 + 2*wpx];
                float2 v0 = *(const float2*)pr;          // cols +0,+1 (kw=0)
                float2 v2 = *(const float2*)(pr + 2);    // cols +2,+3 (kw=2)
                xv[p][0] = pk2(v0.x, v0.y);
                xv[p][1] = pk2(v0.y, v2.x);              // kw=1
                xv[p][2] = pk2(v2.x, v2.y);
            }
            #pragma unroll
            for (int kw = 0; kw < 3; kw++) {
                const float* wq = wbase + (kh*3 + kw)*CCH;
                float4 wa = *(const float4*)wq;
                float4 wb = *(const float4*)(wq + 4);
                unsigned long long wd[8];
                wd[0] = pk2(wa.x, wa.x); wd[1] = pk2(wa.y, wa.y);
                wd[2] = pk2(wa.z, wa.z); wd[3] = pk2(wa.w, wa.w);
                wd[4] = pk2(wb.x, wb.x); wd[5] = pk2(wb.y, wb.y);
                wd[6] = pk2(wb.z, wb.z); wd[7] = pk2(wb.w, wb.w);
                #pragma unroll
                for (int p = 0; p < 2; p++) {
                    #pragma unroll
                    for (int j = 0; j < 8; j++) {
                        FMA2(acc[p][j], xv[p][kw], wd[j]);
                    }
                }
            }
        }
        __syncthreads();
    }

    // LUT1 + pack (two pixels per accumulator)
    float T0[8], D[8];
    #pragma unroll
    for (int j = 0; j < 8; j++) {
        T0[j] = g_lut1_t0[cog*8 + j];
        D[j]  = g_lut1_d[cog*8 + j];
    }
    #pragma unroll
    for (int p = 0; p < 2; p++) {
        int hh = hh0 + 8*p;
        int gh = h0 + hh;
        float av[8][2];
        #pragma unroll
        for (int j = 0; j < 8; j++) upk2(acc[p][j], av[j][0], av[j][1]);
        #pragma unroll
        for (int half = 0; half < 2; half++) {
            int gw = w0 + 2*wpx + half;
            unsigned word0 = 0, word1 = 0;
            #pragma unroll
            for (int j = 0; j < 8; j++) {
                float a = av[j][half];
                int lvl = 0;
                #pragma unroll
                for (int jj = 0; jj < 7; jj++) {
                    float th = T0[j] + (float)jj * D[j];
                    lvl += (jj & 1) ? (a >= th) : (a > th);
                }
                if (j < 4) word0 |= (unsigned)lvl << (8*j);
                else       word1 |= (unsigned)lvl << (8*(j-4));
            }
            size_t base = (((size_t)n*(CCH/4) + cog*2)*HH + gh)*WW + gw;
            g_mid[base]                 = word0;
            g_mid[base + (size_t)HH*WW] = word1;
        }
    }
}

// ---------------------------------------------------------------------------
// Conv2 (exact int8 via dp4a, weights ±1) fused with LUT2 -> fp32 output
// ---------------------------------------------------------------------------
__device__ __forceinline__ unsigned load_mid(const unsigned* __restrict__ mn, int cig,
                                             int idx, int h0, int w0) {
    int ph = idx / 18, pw = idx % 18;
    int gh = h0 - 1 + ph, gw = w0 - 1 + pw;
    if (gh < 0 || gh >= HH || gw < 0 || gw >= WW) return 0u;
    return mn[(size_t)cig*HH*WW + gh*WW + gw];
}

__global__ void __launch_bounds__(256, 2)
conv2_kernel(float* __restrict__ out) {
    __shared__ int ws2[(CCH/4)*9*CCH];     // 9216 B
    __shared__ unsigned patch[2][18*18];

    int n  = blockIdx.z;
    int h0 = blockIdx.y * 16, w0 = blockIdx.x * 16;
    int tid = threadIdx.x;

    for (int i = tid; i < (CCH/4)*9*CCH; i += 256) ws2[i] = g_w2[i];

    int cog = tid >> 6;
    int p0  = tid & 63;

    int acc[4][8];
    #pragma unroll
    for (int p = 0; p < 4; p++)
        #pragma unroll
        for (int j = 0; j < 8; j++) acc[p][j] = 0;

    const unsigned* mn = g_mid + (size_t)n*(CCH/4)*HH*WW;

    unsigned r0 = load_mid(mn, 0, tid, h0, w0);
    unsigned r1 = (tid + 256 < 324) ? load_mid(mn, 0, tid + 256, h0, w0) : 0u;

    for (int cig = 0; cig < CCH/4; cig++) {
        int buf = cig & 1;
        patch[buf][tid] = r0;
        if (tid + 256 < 324) patch[buf][tid + 256] = r1;
        __syncthreads();
        if (cig + 1 < CCH/4) {
            r0 = load_mid(mn, cig + 1, tid, h0, w0);
            r1 = (tid + 256 < 324) ? load_mid(mn, cig + 1, tid + 256, h0, w0) : 0u;
        }
        const int* wp = &ws2[cig*9*CCH + cog*8];
        #pragma unroll
        for (int k = 0; k < 9; k++) {
            int kh = k / 3, kw = k % 3;
            int4 wa = *(const int4*)(wp + k*CCH);
            int4 wb = *(const int4*)(wp + k*CCH + 4);
            #pragma unroll
            for (int p = 0; p < 4; p++) {
                int pix = p0 + 64*p;
                int hh = pix >> 4, wc = pix & 15;
                int xv = (int)patch[buf][(hh + kh)*18 + wc + kw];
                acc[p][0] = __dp4a(xv, wa.x, acc[p][0]);
                acc[p][1] = __dp4a(xv, wa.y, acc[p][1]);
                acc[p][2] = __dp4a(xv, wa.z, acc[p][2]);
                acc[p][3] = __dp4a(xv, wa.w, acc[p][3]);
                acc[p][4] = __dp4a(xv, wb.x, acc[p][4]);
                acc[p][5] = __dp4a(xv, wb.y, acc[p][5]);
                acc[p][6] = __dp4a(xv, wb.z, acc[p][6]);
                acc[p][7] = __dp4a(xv, wb.w, acc[p][7]);
            }
        }
        __syncthreads();
    }

    int IT0[8], ID[8];
    #pragma unroll
    for (int j = 0; j < 8; j++) {
        IT0[j] = g_lut2_t0[cog*8 + j];
        ID[j]  = g_lut2_d[cog*8 + j];
    }
    #pragma unroll
    for (int p = 0; p < 4; p++) {
        int pix = p0 + 64*p;
        int hh = pix >> 4, wc = pix & 15;
        int gh = h0 + hh, gw = w0 + wc;
        #pragma unroll
        for (int j = 0; j < 8; j++) {
            int s = acc[p][j];
            int lvl = 0;
            #pragma unroll
            for (int jj = 0; jj < 7; jj++) {
                int th = IT0[j] + jj * ID[j];
                lvl += (jj & 1) ? (s >= th) : (s > th);
            }
            int co = cog*8 + j;
            out[(((size_t)n*CCH + co)*HH + gh)*WW + gw] = (float)lvl;
        }
    }
}

// ---------------------------------------------------------------------------
extern "C" void kernel_launch(void* const* d_in, const int* in_sizes, int n_in,
                              void* d_out, int out_size) {
    const float* x       = (const float*)d_in[0];
    const float* conv1_w = (const float*)d_in[1];
    const float* conv2_w = (const float*)d_in[2];
    const float* bn1_w   = (const float*)d_in[3];
    const float* bn1_b   = (const float*)d_in[4];
    const float* bn1_m   = (const float*)d_in[5];
    const float* bn1_v   = (const float*)d_in[6];
    const float* bn2_w   = (const float*)d_in[7];
    const float* bn2_b   = (const float*)d_in[8];
    const float* bn2_m   = (const float*)d_in[9];
    const float* bn2_v   = (const float*)d_in[10];
    const float* a1      = (const float*)d_in[11];
    const float* a2      = (const float*)d_in[12];
    const float* ns      = (const float*)d_in[13];

    setup_kernel<<<CCH, KELEMS>>>(conv1_w, conv2_w,
                                  bn1_w, bn1_b, bn1_m, bn1_v,
                                  bn2_w, bn2_b, bn2_m, bn2_v,
                                  a1, a2, ns);

    dim3 grid(WW/16, HH/16, BB);
    conv1_kernel<<<grid, 256>>>(x);
    conv2_kernel<<<grid, 256>>>((float*)d_out);
}